// round 3
// baseline (speedup 1.0000x reference)
#include <cuda_runtime.h>
#include <cuda_bf16.h>
#include <cstdint>

constexpr int NB = 8, C = 64, HW = 4096;
constexpr int QT = 64;                 // q rows per CTA (16 per warp)
constexpr int KT = 64;                 // keys per iteration
constexpr int NKT = HW / KT;           // 64
constexpr float EPS_BN = 1e-5f;
constexpr float QSCALE = 0.125f * 1.4426950408889634f;  // (1/sqrt(64)) * log2(e)

__device__ __align__(256) float g_scale[C];
__device__ __align__(256) float g_shift[C];
__device__ __align__(256) __nv_bfloat16 g_Q[(size_t)NB * HW * C];   // [n,i,c] pre-scaled
__device__ __align__(256) __nv_bfloat16 g_Kb[(size_t)NB * HW * C];  // [n,j,c]
__device__ __align__(256) __nv_bfloat16 g_V[(size_t)NB * C * HW];   // [n,c,j]
__device__ __align__(256) float g_O[(size_t)NB * HW * C];           // [n,i,c]

// ---------- helpers ----------
__device__ __forceinline__ uint32_t smem_u32(const void* p) {
    uint32_t a;
    asm("{ .reg .u64 t; cvta.to.shared.u64 t, %1; cvt.u32.u64 %0, t; }" : "=r"(a) : "l"(p));
    return a;
}
__device__ __forceinline__ float ex2f(float x) {
    float y; asm("ex2.approx.ftz.f32 %0, %1;" : "=f"(y) : "f"(x)); return y;
}
__device__ __forceinline__ void cp_async16(void* s, const void* g) {
    uint32_t sa = smem_u32(s);
    asm volatile("cp.async.cg.shared.global [%0], [%1], 16;" :: "r"(sa), "l"(g));
}
__device__ __forceinline__ void cp_commit() { asm volatile("cp.async.commit_group;"); }

// mma.sync m16n8k16 row.col f32.bf16.bf16.f32, D==C accumulate in-place
__device__ __forceinline__ void mma16816(float* d, const uint32_t* a, uint32_t b0, uint32_t b1) {
    asm volatile(
        "mma.sync.aligned.m16n8k16.row.col.f32.bf16.bf16.f32 "
        "{%0,%1,%2,%3}, {%4,%5,%6,%7}, {%8,%9}, {%0,%1,%2,%3};"
        : "+f"(d[0]), "+f"(d[1]), "+f"(d[2]), "+f"(d[3])
        : "r"(a[0]), "r"(a[1]), "r"(a[2]), "r"(a[3]), "r"(b0), "r"(b1));
}

// ---------- kernel 1: BN stats ----------
__global__ void bn_kernel(const float* __restrict__ x, const float* __restrict__ gamma,
                          const float* __restrict__ beta) {
    int c = blockIdx.x, t = threadIdx.x;
    float s = 0.f, sq = 0.f;
    for (int n = 0; n < NB; n++) {
        const float* p = x + ((size_t)n * C + c) * HW;
        for (int i = t; i < HW; i += 256) { float v = p[i]; s += v; sq += v * v; }
    }
    __shared__ float rs[256], rq[256];
    rs[t] = s; rq[t] = sq; __syncthreads();
    for (int o = 128; o > 0; o >>= 1) {
        if (t < o) { rs[t] += rs[t + o]; rq[t] += rq[t + o]; }
        __syncthreads();
    }
    if (t == 0) {
        float inv = 1.0f / (float)(NB * HW);
        float mean = rs[0] * inv;
        float var = rq[0] * inv - mean * mean;
        float sc = rsqrtf(var + EPS_BN) * gamma[c];
        g_scale[c] = sc;
        g_shift[c] = beta[c] - mean * sc;
    }
}

// ---------- kernel 2: BN-apply + QKV ----------
__global__ __launch_bounds__(128) void qkv_kernel(
    const float* __restrict__ x,
    const float* __restrict__ wq, const float* __restrict__ bq,
    const float* __restrict__ wk, const float* __restrict__ bk,
    const float* __restrict__ wv, const float* __restrict__ bv) {
    __shared__ float sW[C * C];              // transposed: sW[c*64+o]
    __shared__ __nv_bfloat16 sV[C][136];
    int t = threadIdx.x;
    int n = blockIdx.x >> 5;
    int i0 = (blockIdx.x & 31) * 128;
    int i = i0 + t;

    float xn[C];
#pragma unroll
    for (int c = 0; c < C; c++)
        xn[c] = x[((size_t)n * C + c) * HW + i] * g_scale[c] + g_shift[c];

    // Q (pre-scaled by QSCALE)
    for (int j = t; j < C * C; j += 128) sW[(j & 63) * C + (j >> 6)] = wq[j];
    __syncthreads();
    {
        uint4* row = reinterpret_cast<uint4*>(g_Q + ((size_t)n * HW + i) * C);
#pragma unroll 1
        for (int og = 0; og < 8; og++) {
            float acc[8];
#pragma unroll
            for (int u = 0; u < 8; u++) acc[u] = bq[og * 8 + u];
#pragma unroll
            for (int c = 0; c < C; c++) {
                float xv = xn[c];
#pragma unroll
                for (int u = 0; u < 8; u++) acc[u] += sW[c * C + og * 8 + u] * xv;
            }
            uint32_t pk[4];
#pragma unroll
            for (int u = 0; u < 4; u++) {
                __nv_bfloat162 b = __floats2bfloat162_rn(acc[2 * u] * QSCALE, acc[2 * u + 1] * QSCALE);
                pk[u] = *reinterpret_cast<uint32_t*>(&b);
            }
            row[og] = make_uint4(pk[0], pk[1], pk[2], pk[3]);
        }
    }
    __syncthreads();

    // K
    for (int j = t; j < C * C; j += 128) sW[(j & 63) * C + (j >> 6)] = wk[j];
    __syncthreads();
    {
        uint4* row = reinterpret_cast<uint4*>(g_Kb + ((size_t)n * HW + i) * C);
#pragma unroll 1
        for (int og = 0; og < 8; og++) {
            float acc[8];
#pragma unroll
            for (int u = 0; u < 8; u++) acc[u] = bk[og * 8 + u];
#pragma unroll
            for (int c = 0; c < C; c++) {
                float xv = xn[c];
#pragma unroll
                for (int u = 0; u < 8; u++) acc[u] += sW[c * C + og * 8 + u] * xv;
            }
            uint32_t pk[4];
#pragma unroll
            for (int u = 0; u < 4; u++) {
                __nv_bfloat162 b = __floats2bfloat162_rn(acc[2 * u], acc[2 * u + 1]);
                pk[u] = *reinterpret_cast<uint32_t*>(&b);
            }
            row[og] = make_uint4(pk[0], pk[1], pk[2], pk[3]);
        }
    }
    __syncthreads();

    // V (transposed to [n,c,j])
    for (int j = t; j < C * C; j += 128) sW[(j & 63) * C + (j >> 6)] = wv[j];
    __syncthreads();
#pragma unroll 1
    for (int og = 0; og < 8; og++) {
        float acc[8];
#pragma unroll
        for (int u = 0; u < 8; u++) acc[u] = bv[og * 8 + u];
#pragma unroll
        for (int c = 0; c < C; c++) {
            float xv = xn[c];
#pragma unroll
            for (int u = 0; u < 8; u++) acc[u] += sW[c * C + og * 8 + u] * xv;
        }
#pragma unroll
        for (int u = 0; u < 8; u++) sV[og * 8 + u][t] = __float2bfloat16(acc[u]);
    }
    __syncthreads();
    for (int c = 0; c < C; c++)
        g_V[((size_t)n * C + c) * HW + i0 + t] = sV[c][t];
}

// ---------- kernel 3: flash attention on mma.sync (HMMA bf16) ----------
constexpr int ROWB = 144;  // 64 ch * 2B padded to 144B -> conflict-free B-frag loads

__global__ __launch_bounds__(128) void attn_kernel() {
    __shared__ __align__(16) char sK[2][KT * ROWB];  // [key][ch]
    __shared__ __align__(16) char sV[2][C * ROWB];   // [ch][key]
    int t = threadIdx.x, wid = t >> 5, lane = t & 31;
    int n = blockIdx.y, qt = blockIdx.x;
    int qrow0 = qt * QT + wid * 16;
    int m = lane >> 2;            // row within fragment
    int qp = (lane & 3) * 2;      // col pair base

    const __nv_bfloat16* Kg = g_Kb + (size_t)n * HW * C;        // [j][c]
    const __nv_bfloat16* Vg = g_V + (size_t)n * C * HW;         // [c][j]

    // Q fragments (loop-invariant): qa[kstep][0..3]
    uint32_t qa[4][4];
    {
        const __nv_bfloat16* Qb = g_Q + ((size_t)n * HW + qrow0) * C;
#pragma unroll
        for (int kb = 0; kb < 4; kb++) {
            qa[kb][0] = *(const uint32_t*)(Qb + (size_t)m * C + kb * 16 + qp);
            qa[kb][1] = *(const uint32_t*)(Qb + (size_t)(m + 8) * C + kb * 16 + qp);
            qa[kb][2] = *(const uint32_t*)(Qb + (size_t)m * C + kb * 16 + 8 + qp);
            qa[kb][3] = *(const uint32_t*)(Qb + (size_t)(m + 8) * C + kb * 16 + 8 + qp);
        }
    }

    float oacc[8][4];
#pragma unroll
    for (int i = 0; i < 8; i++)
#pragma unroll
        for (int j = 0; j < 4; j++) oacc[i][j] = 0.f;
    float lsum0 = 0.f, lsum1 = 0.f;

    // prefetch tile kt into buffer b
    auto prefetch = [&](int b, int kt) {
#pragma unroll
        for (int r = 0; r < 4; r++) {
            int ch = t + r * 128;           // 0..511 : 16B chunks
            int row = ch >> 3, col = ch & 7;
            cp_async16(sK[b] + row * ROWB + col * 16,
                       Kg + ((size_t)(kt * KT + row)) * C + col * 8);
            cp_async16(sV[b] + row * ROWB + col * 16,
                       Vg + (size_t)row * HW + kt * KT + col * 8);
        }
        cp_commit();
    };

    prefetch(0, 0);

    for (int kt = 0; kt < NKT; kt++) {
        if (kt + 1 < NKT) {
            prefetch((kt + 1) & 1, kt + 1);
            asm volatile("cp.async.wait_group 1;");
        } else {
            asm volatile("cp.async.wait_group 0;");
        }
        __syncthreads();
        const char* kb_s = sK[kt & 1];
        const char* vb_s = sV[kt & 1];

        // MMA1: S[16 x 64keys] = Q * K^T
        float sacc[8][4];
#pragma unroll
        for (int nt = 0; nt < 8; nt++) {
#pragma unroll
            for (int j = 0; j < 4; j++) sacc[nt][j] = 0.f;
#pragma unroll
            for (int kb = 0; kb < 4; kb++) {
                const char* base = kb_s + (nt * 8 + m) * ROWB + (kb * 16 + qp) * 2;
                uint32_t b0 = *(const uint32_t*)(base);
                uint32_t b1 = *(const uint32_t*)(base + 16);
                mma16816(sacc[nt], qa[kb], b0, b1);
            }
        }

        // exp2 + rowsum + pack into P A-fragments
        uint32_t pa[4][4];
#pragma unroll
        for (int kc = 0; kc < 4; kc++) {
#pragma unroll
            for (int h = 0; h < 2; h++) {
                float e0 = ex2f(sacc[2 * kc + h][0]);
                float e1 = ex2f(sacc[2 * kc + h][1]);
                float e2 = ex2f(sacc[2 * kc + h][2]);
                float e3 = ex2f(sacc[2 * kc + h][3]);
                lsum0 += e0 + e1;
                lsum1 += e2 + e3;
                __nv_bfloat162 p01 = __floats2bfloat162_rn(e0, e1);
                __nv_bfloat162 p23 = __floats2bfloat162_rn(e2, e3);
                pa[kc][h * 2 + 0] = *reinterpret_cast<uint32_t*>(&p01);
                pa[kc][h * 2 + 1] = *reinterpret_cast<uint32_t*>(&p23);
            }
        }

        // MMA2: O[16 x 64ch] += P * V^T
#pragma unroll
        for (int ct = 0; ct < 8; ct++) {
#pragma unroll
            for (int kc = 0; kc < 4; kc++) {
                const char* base = vb_s + (ct * 8 + m) * ROWB + (kc * 16 + qp) * 2;
                uint32_t b0 = *(const uint32_t*)(base);
                uint32_t b1 = *(const uint32_t*)(base + 16);
                mma16816(oacc[ct], pa[kc], b0, b1);
            }
        }
        __syncthreads();
    }

    // reduce row sums across the 4 lanes sharing each row
    lsum0 += __shfl_xor_sync(0xffffffffu, lsum0, 1);
    lsum0 += __shfl_xor_sync(0xffffffffu, lsum0, 2);
    lsum1 += __shfl_xor_sync(0xffffffffu, lsum1, 1);
    lsum1 += __shfl_xor_sync(0xffffffffu, lsum1, 2);
    float inv0 = 1.f / lsum0, inv1 = 1.f / lsum1;

    float* orow0 = g_O + ((size_t)n * HW + qrow0 + m) * C;
    float* orow1 = orow0 + 8 * C;
#pragma unroll
    for (int ct = 0; ct < 8; ct++) {
        int col = ct * 8 + qp;
        float2 v0 = make_float2(oacc[ct][0] * inv0, oacc[ct][1] * inv0);
        float2 v1 = make_float2(oacc[ct][2] * inv1, oacc[ct][3] * inv1);
        *reinterpret_cast<float2*>(orow0 + col) = v0;
        *reinterpret_cast<float2*>(orow1 + col) = v1;
    }
}

// ---------- kernel 4: output conv + residual ----------
__global__ __launch_bounds__(128) void out_kernel(
    const float* __restrict__ x, const float* __restrict__ wo,
    const float* __restrict__ bo, float* __restrict__ out) {
    __shared__ float sW[C * C];
    int t = threadIdx.x;
    int n = blockIdx.y;
    int p = blockIdx.x * 128 + t;
    for (int j = t; j < C * C; j += 128) sW[(j & 63) * C + (j >> 6)] = wo[j];
    __syncthreads();
    float v[C];
#pragma unroll
    for (int c = 0; c < C; c++) v[c] = g_O[((size_t)n * C + c) * HW + p];  // raw-reshape view
#pragma unroll 1
    for (int og = 0; og < 8; og++) {
        float acc[8];
#pragma unroll
        for (int u = 0; u < 8; u++) acc[u] = bo[og * 8 + u];
#pragma unroll
        for (int c = 0; c < C; c++) {
            float xv = v[c];
#pragma unroll
            for (int u = 0; u < 8; u++) acc[u] += sW[c * C + og * 8 + u] * xv;
        }
#pragma unroll
        for (int u = 0; u < 8; u++) {
            int o = og * 8 + u;
            out[((size_t)n * C + o) * HW + p] = acc[u] + x[((size_t)n * C + o) * HW + p];
        }
    }
}

extern "C" void kernel_launch(void* const* d_in, const int* in_sizes, int n_in,
                              void* d_out, int out_size) {
    const float* x     = (const float*)d_in[0];
    const float* gamma = (const float*)d_in[1];
    const float* beta  = (const float*)d_in[2];
    const float* wq    = (const float*)d_in[3];
    const float* bq    = (const float*)d_in[4];
    const float* wk    = (const float*)d_in[5];
    const float* bk    = (const float*)d_in[6];
    const float* wv    = (const float*)d_in[7];
    const float* bv    = (const float*)d_in[8];
    const float* wo    = (const float*)d_in[9];
    const float* bo    = (const float*)d_in[10];
    float* out = (float*)d_out;

    bn_kernel<<<C, 256>>>(x, gamma, beta);
    qkv_kernel<<<NB * 32, 128>>>(x, wq, bq, wk, bk, wv, bv);
    attn_kernel<<<dim3(HW / QT, NB), 128>>>();
    out_kernel<<<dim3(HW / 128, NB), 128>>>(x, wo, bo, out);
}

// round 4
// speedup vs baseline: 1.0531x; 1.0531x over previous
#include <cuda_runtime.h>
#include <cuda_bf16.h>
#include <cstdint>

constexpr int NB = 8, C = 64, HW = 4096;
constexpr int QT = 64;                 // q rows per CTA (16 per warp)
constexpr int KT = 64;                 // keys per iteration
constexpr int NKT = HW / KT;           // 64
constexpr float EPS_BN = 1e-5f;
constexpr float QSCALE = 0.125f * 1.4426950408889634f;  // (1/sqrt(64)) * log2(e)

__device__ __align__(256) float g_scale[C];
__device__ __align__(256) float g_shift[C];
__device__ __align__(256) __nv_bfloat16 g_Q[(size_t)NB * HW * C];   // [n,i,c] pre-scaled
__device__ __align__(256) __nv_bfloat16 g_Kb[(size_t)NB * HW * C];  // [n,j,c]
__device__ __align__(256) __nv_bfloat16 g_V[(size_t)NB * C * HW];   // [n,c,j]
__device__ __align__(256) float g_O[(size_t)NB * HW * C];           // [n,i,c]

// ---------- helpers ----------
__device__ __forceinline__ uint32_t smem_u32(const void* p) {
    uint32_t a;
    asm("{ .reg .u64 t; cvta.to.shared.u64 t, %1; cvt.u32.u64 %0, t; }" : "=r"(a) : "l"(p));
    return a;
}
__device__ __forceinline__ float ex2f(float x) {
    float y; asm("ex2.approx.ftz.f32 %0, %1;" : "=f"(y) : "f"(x)); return y;
}
__device__ __forceinline__ void cp_async16(uint32_t s, const void* g) {
    asm volatile("cp.async.cg.shared.global [%0], [%1], 16;" :: "r"(s), "l"(g));
}
__device__ __forceinline__ void cp_commit() { asm volatile("cp.async.commit_group;"); }

__device__ __forceinline__ void mma16816(float* d, const uint32_t* a, uint32_t b0, uint32_t b1) {
    asm volatile(
        "mma.sync.aligned.m16n8k16.row.col.f32.bf16.bf16.f32 "
        "{%0,%1,%2,%3}, {%4,%5,%6,%7}, {%8,%9}, {%0,%1,%2,%3};"
        : "+f"(d[0]), "+f"(d[1]), "+f"(d[2]), "+f"(d[3])
        : "r"(a[0]), "r"(a[1]), "r"(a[2]), "r"(a[3]), "r"(b0), "r"(b1));
}
__device__ __forceinline__ void ldsm4(uint32_t* r, uint32_t addr) {
    asm volatile("ldmatrix.sync.aligned.m8n8.x4.shared.b16 {%0,%1,%2,%3}, [%4];"
        : "=r"(r[0]), "=r"(r[1]), "=r"(r[2]), "=r"(r[3]) : "r"(addr));
}

// ---------- kernel 1: BN stats ----------
__global__ void bn_kernel(const float* __restrict__ x, const float* __restrict__ gamma,
                          const float* __restrict__ beta) {
    int c = blockIdx.x, t = threadIdx.x;
    float s = 0.f, sq = 0.f;
    for (int n = 0; n < NB; n++) {
        const float* p = x + ((size_t)n * C + c) * HW;
        for (int i = t; i < HW; i += 256) { float v = p[i]; s += v; sq += v * v; }
    }
    __shared__ float rs[256], rq[256];
    rs[t] = s; rq[t] = sq; __syncthreads();
    for (int o = 128; o > 0; o >>= 1) {
        if (t < o) { rs[t] += rs[t + o]; rq[t] += rq[t + o]; }
        __syncthreads();
    }
    if (t == 0) {
        float inv = 1.0f / (float)(NB * HW);
        float mean = rs[0] * inv;
        float var = rq[0] * inv - mean * mean;
        float sc = rsqrtf(var + EPS_BN) * gamma[c];
        g_scale[c] = sc;
        g_shift[c] = beta[c] - mean * sc;
    }
}

// ---------- kernel 2: BN-apply + QKV ----------
__global__ __launch_bounds__(128) void qkv_kernel(
    const float* __restrict__ x,
    const float* __restrict__ wq, const float* __restrict__ bq,
    const float* __restrict__ wk, const float* __restrict__ bk,
    const float* __restrict__ wv, const float* __restrict__ bv) {
    __shared__ float sW[C * C];              // transposed: sW[c*64+o]
    __shared__ __nv_bfloat16 sV[C][136];
    int t = threadIdx.x;
    int n = blockIdx.x >> 5;
    int i0 = (blockIdx.x & 31) * 128;
    int i = i0 + t;

    float xn[C];
#pragma unroll
    for (int c = 0; c < C; c++)
        xn[c] = x[((size_t)n * C + c) * HW + i] * g_scale[c] + g_shift[c];

    // Q (pre-scaled by QSCALE)
    for (int j = t; j < C * C; j += 128) sW[(j & 63) * C + (j >> 6)] = wq[j];
    __syncthreads();
    {
        uint4* row = reinterpret_cast<uint4*>(g_Q + ((size_t)n * HW + i) * C);
#pragma unroll 1
        for (int og = 0; og < 8; og++) {
            float acc[8];
#pragma unroll
            for (int u = 0; u < 8; u++) acc[u] = bq[og * 8 + u];
#pragma unroll
            for (int c = 0; c < C; c++) {
                float xv = xn[c];
#pragma unroll
                for (int u = 0; u < 8; u++) acc[u] += sW[c * C + og * 8 + u] * xv;
            }
            uint32_t pk[4];
#pragma unroll
            for (int u = 0; u < 4; u++) {
                __nv_bfloat162 b = __floats2bfloat162_rn(acc[2 * u] * QSCALE, acc[2 * u + 1] * QSCALE);
                pk[u] = *reinterpret_cast<uint32_t*>(&b);
            }
            row[og] = make_uint4(pk[0], pk[1], pk[2], pk[3]);
        }
    }
    __syncthreads();

    // K
    for (int j = t; j < C * C; j += 128) sW[(j & 63) * C + (j >> 6)] = wk[j];
    __syncthreads();
    {
        uint4* row = reinterpret_cast<uint4*>(g_Kb + ((size_t)n * HW + i) * C);
#pragma unroll 1
        for (int og = 0; og < 8; og++) {
            float acc[8];
#pragma unroll
            for (int u = 0; u < 8; u++) acc[u] = bk[og * 8 + u];
#pragma unroll
            for (int c = 0; c < C; c++) {
                float xv = xn[c];
#pragma unroll
                for (int u = 0; u < 8; u++) acc[u] += sW[c * C + og * 8 + u] * xv;
            }
            uint32_t pk[4];
#pragma unroll
            for (int u = 0; u < 4; u++) {
                __nv_bfloat162 b = __floats2bfloat162_rn(acc[2 * u], acc[2 * u + 1]);
                pk[u] = *reinterpret_cast<uint32_t*>(&b);
            }
            row[og] = make_uint4(pk[0], pk[1], pk[2], pk[3]);
        }
    }
    __syncthreads();

    // V (transposed to [n,c,j])
    for (int j = t; j < C * C; j += 128) sW[(j & 63) * C + (j >> 6)] = wv[j];
    __syncthreads();
#pragma unroll 1
    for (int og = 0; og < 8; og++) {
        float acc[8];
#pragma unroll
        for (int u = 0; u < 8; u++) acc[u] = bv[og * 8 + u];
#pragma unroll
        for (int c = 0; c < C; c++) {
            float xv = xn[c];
#pragma unroll
            for (int u = 0; u < 8; u++) acc[u] += sW[c * C + og * 8 + u] * xv;
        }
#pragma unroll
        for (int u = 0; u < 8; u++) sV[og * 8 + u][t] = __float2bfloat16(acc[u]);
    }
    __syncthreads();
    for (int c = 0; c < C; c++)
        g_V[((size_t)n * C + c) * HW + i0 + t] = sV[c][t];
}

// ---------- kernel 3: flash attention on mma.sync + ldmatrix ----------
constexpr int ROWB = 144;  // 64 ch * 2B padded to 144B -> conflict-free ldmatrix rows

__global__ __launch_bounds__(128) void attn_kernel() {
    __shared__ __align__(16) char sK[2][KT * ROWB];  // [key][ch]
    __shared__ __align__(16) char sV[2][C * ROWB];   // [ch][key]
    int t = threadIdx.x, wid = t >> 5, lane = t & 31;
    int n = blockIdx.y, qt = blockIdx.x;
    int qrow0 = qt * QT + wid * 16;
    int m = lane >> 2;            // row within fragment
    int qp = (lane & 3) * 2;      // col pair base

    const __nv_bfloat16* Kg = g_Kb + (size_t)n * HW * C;        // [j][c]
    const __nv_bfloat16* Vg = g_V + (size_t)n * C * HW;         // [c][j]

    // per-lane ldmatrix offset: lane l -> matrix (l>>3), row (l&7)
    uint32_t lds_off = (uint32_t)((lane & 7) * ROWB + (lane >> 3) * 16);
    uint32_t sKa = smem_u32(sK);
    uint32_t sVa = smem_u32(sV);

    // Q fragments (loop-invariant): qa[kstep][0..3]
    uint32_t qa[4][4];
    {
        const __nv_bfloat16* Qb = g_Q + ((size_t)n * HW + qrow0) * C;
#pragma unroll
        for (int kb = 0; kb < 4; kb++) {
            qa[kb][0] = *(const uint32_t*)(Qb + (size_t)m * C + kb * 16 + qp);
            qa[kb][1] = *(const uint32_t*)(Qb + (size_t)(m + 8) * C + kb * 16 + qp);
            qa[kb][2] = *(const uint32_t*)(Qb + (size_t)m * C + kb * 16 + 8 + qp);
            qa[kb][3] = *(const uint32_t*)(Qb + (size_t)(m + 8) * C + kb * 16 + 8 + qp);
        }
    }

    float oacc[8][4];
#pragma unroll
    for (int i = 0; i < 8; i++)
#pragma unroll
        for (int j = 0; j < 4; j++) oacc[i][j] = 0.f;
    float lsum0 = 0.f, lsum1 = 0.f;

    auto prefetch = [&](int b, int kt) {
#pragma unroll
        for (int r = 0; r < 4; r++) {
            int ch = t + r * 128;           // 0..511 : 16B chunks
            int row = ch >> 3, col = ch & 7;
            cp_async16(sKa + (uint32_t)(b * KT * ROWB + row * ROWB + col * 16),
                       Kg + ((size_t)(kt * KT + row)) * C + col * 8);
            cp_async16(sVa + (uint32_t)(b * C * ROWB + row * ROWB + col * 16),
                       Vg + (size_t)row * HW + kt * KT + col * 8);
        }
        cp_commit();
    };

    prefetch(0, 0);

    for (int kt = 0; kt < NKT; kt++) {
        asm volatile("cp.async.wait_group 0;");
        __syncthreads();                       // tile kt visible; prior tile reads all done
        if (kt + 1 < NKT) prefetch((kt + 1) & 1, kt + 1);

        uint32_t kb_a = sKa + (uint32_t)((kt & 1) * KT * ROWB) + lds_off;
        uint32_t vb_a = sVa + (uint32_t)((kt & 1) * C * ROWB) + lds_off;

        // MMA1: S[16 x 64keys] = Q * K^T
        float sacc[8][4];
#pragma unroll
        for (int nt = 0; nt < 8; nt++) {
#pragma unroll
            for (int j = 0; j < 4; j++) sacc[nt][j] = 0.f;
            uint32_t B[8];
            ldsm4(B, kb_a + nt * 8 * ROWB);        // kb 0,1 (ch 0..31)
            ldsm4(B + 4, kb_a + nt * 8 * ROWB + 64); // kb 2,3 (ch 32..63)
            mma16816(sacc[nt], qa[0], B[0], B[1]);
            mma16816(sacc[nt], qa[1], B[2], B[3]);
            mma16816(sacc[nt], qa[2], B[4], B[5]);
            mma16816(sacc[nt], qa[3], B[6], B[7]);
        }

        // exp2 + rowsum + pack into P A-fragments
        uint32_t pa[4][4];
#pragma unroll
        for (int kc = 0; kc < 4; kc++) {
#pragma unroll
            for (int h = 0; h < 2; h++) {
                float e0 = ex2f(sacc[2 * kc + h][0]);
                float e1 = ex2f(sacc[2 * kc + h][1]);
                float e2 = ex2f(sacc[2 * kc + h][2]);
                float e3 = ex2f(sacc[2 * kc + h][3]);
                lsum0 += e0 + e1;
                lsum1 += e2 + e3;
                __nv_bfloat162 p01 = __floats2bfloat162_rn(e0, e1);
                __nv_bfloat162 p23 = __floats2bfloat162_rn(e2, e3);
                pa[kc][h * 2 + 0] = *reinterpret_cast<uint32_t*>(&p01);
                pa[kc][h * 2 + 1] = *reinterpret_cast<uint32_t*>(&p23);
            }
        }

        // MMA2: O[16 x 64ch] += P * V^T
#pragma unroll
        for (int ct = 0; ct < 8; ct++) {
            uint32_t B[8];
            ldsm4(B, vb_a + ct * 8 * ROWB);          // kc 0,1 (keys 0..31)
            ldsm4(B + 4, vb_a + ct * 8 * ROWB + 64); // kc 2,3 (keys 32..63)
            mma16816(oacc[ct], pa[0], B[0], B[1]);
            mma16816(oacc[ct], pa[1], B[2], B[3]);
            mma16816(oacc[ct], pa[2], B[4], B[5]);
            mma16816(oacc[ct], pa[3], B[6], B[7]);
        }
    }

    // reduce row sums across the 4 lanes sharing each row
    lsum0 += __shfl_xor_sync(0xffffffffu, lsum0, 1);
    lsum0 += __shfl_xor_sync(0xffffffffu, lsum0, 2);
    lsum1 += __shfl_xor_sync(0xffffffffu, lsum1, 1);
    lsum1 += __shfl_xor_sync(0xffffffffu, lsum1, 2);
    float inv0 = 1.f / lsum0, inv1 = 1.f / lsum1;

    float* orow0 = g_O + ((size_t)n * HW + qrow0 + m) * C;
    float* orow1 = orow0 + 8 * C;
#pragma unroll
    for (int ct = 0; ct < 8; ct++) {
        int col = ct * 8 + qp;
        float2 v0 = make_float2(oacc[ct][0] * inv0, oacc[ct][1] * inv0);
        float2 v1 = make_float2(oacc[ct][2] * inv1, oacc[ct][3] * inv1);
        *reinterpret_cast<float2*>(orow0 + col) = v0;
        *reinterpret_cast<float2*>(orow1 + col) = v1;
    }
}

// ---------- kernel 4: output conv + residual (smem-staged, hi-occupancy) ----------
constexpr int OP = 64;   // positions per block
__global__ __launch_bounds__(256) void out_kernel(
    const float* __restrict__ x, const float* __restrict__ wo,
    const float* __restrict__ bo, float* __restrict__ out) {
    __shared__ float sW[C * C];        // transposed: sW[c*64+o]
    __shared__ __align__(16) float sv[C][OP];
    int t = threadIdx.x;
    int n = blockIdx.y;
    int p0 = blockIdx.x * OP;

    for (int j = t; j < C * C; j += 256) sW[(j & 63) * C + (j >> 6)] = wo[j];
    {
        const float* Ob = g_O + (size_t)n * C * HW + p0;   // raw-reshape view [n][c][p]
        for (int j = t; j < C * 16; j += 256) {
            int c = j >> 4, w = j & 15;
            float4 v = *reinterpret_cast<const float4*>(Ob + (size_t)c * HW + w * 4);
            *reinterpret_cast<float4*>(&sv[c][w * 4]) = v;
        }
    }
    __syncthreads();

    int g = t >> 6, pl = t & 63, p = p0 + pl;
    float acc[16];
#pragma unroll
    for (int o = 0; o < 16; o++) acc[o] = bo[g * 16 + o];
#pragma unroll
    for (int c = 0; c < C; c++) {
        float xv = sv[c][pl];
#pragma unroll
        for (int o = 0; o < 16; o++) acc[o] += sW[c * C + g * 16 + o] * xv;
    }
    const float* xb = x + (size_t)n * C * HW + p;
    float* ob = out + (size_t)n * C * HW + p;
#pragma unroll
    for (int o = 0; o < 16; o++) {
        size_t off = (size_t)(g * 16 + o) * HW;
        ob[off] = acc[o] + xb[off];
    }
}

extern "C" void kernel_launch(void* const* d_in, const int* in_sizes, int n_in,
                              void* d_out, int out_size) {
    const float* x     = (const float*)d_in[0];
    const float* gamma = (const float*)d_in[1];
    const float* beta  = (const float*)d_in[2];
    const float* wq    = (const float*)d_in[3];
    const float* bq    = (const float*)d_in[4];
    const float* wk    = (const float*)d_in[5];
    const float* bk    = (const float*)d_in[6];
    const float* wv    = (const float*)d_in[7];
    const float* bv    = (const float*)d_in[8];
    const float* wo    = (const float*)d_in[9];
    const float* bo    = (const float*)d_in[10];
    float* out = (float*)d_out;

    bn_kernel<<<C, 256>>>(x, gamma, beta);
    qkv_kernel<<<NB * 32, 128>>>(x, wq, bq, wk, bk, wv, bv);
    attn_kernel<<<dim3(HW / QT, NB), 128>>>();
    out_kernel<<<dim3(HW / OP, NB), 256>>>(x, wo, bo, out);
}

// round 5
// speedup vs baseline: 1.3565x; 1.2881x over previous
#include <cuda_runtime.h>
#include <cuda_bf16.h>
#include <cstdint>

constexpr int NB = 8, C = 64, HW = 4096;
constexpr int QT = 64;                 // q rows per CTA (16 per warp)
constexpr int KT = 64;                 // keys per iteration
constexpr int NKT = HW / KT;           // 64
constexpr float EPS_BN = 1e-5f;
constexpr float QSCALE = 0.125f * 1.4426950408889634f;  // (1/sqrt(64)) * log2(e)

__device__ __align__(256) float g_scale[C];
__device__ __align__(256) float g_shift[C];
__device__ __align__(256) float g_ps[512];
__device__ __align__(256) float g_pq[512];
__device__ __align__(256) __nv_bfloat16 g_Q[(size_t)NB * HW * C];   // [n,i,c] pre-scaled
__device__ __align__(256) __nv_bfloat16 g_Kb[(size_t)NB * HW * C];  // [n,j,c]
__device__ __align__(256) __nv_bfloat16 g_V[(size_t)NB * HW * C];   // [n,j,c]  (same layout as K!)
__device__ __align__(256) float g_O[(size_t)NB * HW * C];           // [n,i,c]

// ---------- helpers ----------
__device__ __forceinline__ uint32_t smem_u32(const void* p) {
    uint32_t a;
    asm("{ .reg .u64 t; cvta.to.shared.u64 t, %1; cvt.u32.u64 %0, t; }" : "=r"(a) : "l"(p));
    return a;
}
__device__ __forceinline__ float ex2f(float x) {
    float y; asm("ex2.approx.ftz.f32 %0, %1;" : "=f"(y) : "f"(x)); return y;
}
__device__ __forceinline__ void cp_async16(uint32_t s, const void* g) {
    asm volatile("cp.async.cg.shared.global [%0], [%1], 16;" :: "r"(s), "l"(g));
}
__device__ __forceinline__ void cp_commit() { asm volatile("cp.async.commit_group;"); }

__device__ __forceinline__ void mma16816(float* d, const uint32_t* a, uint32_t b0, uint32_t b1) {
    asm volatile(
        "mma.sync.aligned.m16n8k16.row.col.f32.bf16.bf16.f32 "
        "{%0,%1,%2,%3}, {%4,%5,%6,%7}, {%8,%9}, {%0,%1,%2,%3};"
        : "+f"(d[0]), "+f"(d[1]), "+f"(d[2]), "+f"(d[3])
        : "r"(a[0]), "r"(a[1]), "r"(a[2]), "r"(a[3]), "r"(b0), "r"(b1));
}
__device__ __forceinline__ void ldsm4(uint32_t* r, uint32_t addr) {
    asm volatile("ldmatrix.sync.aligned.m8n8.x4.shared.b16 {%0,%1,%2,%3}, [%4];"
        : "=r"(r[0]), "=r"(r[1]), "=r"(r[2]), "=r"(r[3]) : "r"(addr));
}
__device__ __forceinline__ void ldsm4t(uint32_t* r, uint32_t addr) {
    asm volatile("ldmatrix.sync.aligned.m8n8.x4.trans.shared.b16 {%0,%1,%2,%3}, [%4];"
        : "=r"(r[0]), "=r"(r[1]), "=r"(r[2]), "=r"(r[3]) : "r"(addr));
}
__device__ __forceinline__ uint32_t packbf(float a, float b) {
    __nv_bfloat162 t = __floats2bfloat162_rn(a, b);
    return *reinterpret_cast<uint32_t*>(&t);
}

// ---------- kernel 1a: BN partial sums ----------
__global__ __launch_bounds__(256) void bn_part(const float* __restrict__ x) {
    int c = blockIdx.x >> 3, s = blockIdx.x & 7, t = threadIdx.x;
    const float* p = x + ((size_t)s * C + c) * HW;
    float sm = 0.f, sq = 0.f;
#pragma unroll
    for (int i = 0; i < HW / 256; i++) { float v = p[t + i * 256]; sm += v; sq += v * v; }
    __shared__ float rs[256], rq[256];
    rs[t] = sm; rq[t] = sq; __syncthreads();
    for (int o = 128; o > 0; o >>= 1) {
        if (t < o) { rs[t] += rs[t + o]; rq[t] += rq[t + o]; }
        __syncthreads();
    }
    if (t == 0) { g_ps[c * 8 + s] = rs[0]; g_pq[c * 8 + s] = rq[0]; }
}

// ---------- kernel 1b: BN finalize ----------
__global__ void bn_fin(const float* __restrict__ gamma, const float* __restrict__ beta) {
    int c = threadIdx.x;
    float sm = 0.f, sq = 0.f;
#pragma unroll
    for (int k = 0; k < 8; k++) { sm += g_ps[c * 8 + k]; sq += g_pq[c * 8 + k]; }
    float inv = 1.0f / (float)(NB * HW);
    float mean = sm * inv;
    float var = sq * inv - mean * mean;
    float sc = rsqrtf(var + EPS_BN) * gamma[c];
    g_scale[c] = sc;
    g_shift[c] = beta[c] - mean * sc;
}

// ---------- kernel 2: BN-apply + QKV via HMMA ----------
// sX: 128 rows x 128B (SW128-xor swizzled), sW[3]: 64 rows x 128B each
__global__ __launch_bounds__(128) void qkv_kernel(
    const float* __restrict__ x,
    const float* __restrict__ wq, const float* __restrict__ bq,
    const float* __restrict__ wk, const float* __restrict__ bk,
    const float* __restrict__ wv, const float* __restrict__ bv) {
    __shared__ __align__(16) char sX[128 * 128];
    __shared__ __align__(16) char sW[3][64 * 128];
    int t = threadIdx.x, wid = t >> 5, l = t & 31;
    int n = blockIdx.y;
    int p0 = blockIdx.x * 128;
    uint32_t sXa = smem_u32(sX);

    // stage x (normalized, bf16, swizzled): thread t owns row p=t
    {
        const float* xb = x + (size_t)n * C * HW + p0 + t;
        uint32_t rowa = sXa + (uint32_t)t * 128;
        int r7 = t & 7;
#pragma unroll
        for (int cp = 0; cp < 32; cp++) {
            int c0 = 2 * cp;
            float v0 = xb[(size_t)c0 * HW] * g_scale[c0] + g_shift[c0];
            float v1 = xb[(size_t)(c0 + 1) * HW] * g_scale[c0 + 1] + g_shift[c0 + 1];
            uint32_t pk = packbf(v0, v1);
            uint32_t off = ((uint32_t)(((c0 >> 3) ^ r7) << 4)) + (uint32_t)((c0 & 7) * 2);
            *reinterpret_cast<uint32_t*>(&((char*)sX)[t * 128 + off]) = pk;
        }
    }
    // stage weights (bf16, swizzled)
    {
        const float* ws[3] = {wq, wk, wv};
#pragma unroll
        for (int w = 0; w < 3; w++) {
            const float* wp = ws[w];
#pragma unroll
            for (int i = 0; i < 16; i++) {
                int idx = t + i * 128;          // 0..2047 pairs
                int o = idx >> 5, cp = idx & 31, c0 = 2 * cp;
                float2 wv2 = *reinterpret_cast<const float2*>(wp + o * 64 + c0);
                uint32_t pk = packbf(wv2.x, wv2.y);
                uint32_t off = ((uint32_t)(((c0 >> 3) ^ (o & 7)) << 4)) + (uint32_t)((c0 & 7) * 2);
                *reinterpret_cast<uint32_t*>(&sW[w][o * 128 + off]) = pk;
            }
        }
    }
    __syncthreads();

    // A fragments: warp owns mtiles {2*wid, 2*wid+1} (rows wid*32 .. wid*32+31)
    uint32_t A[2][4][4];
    {
        int arow = (l & 7) + ((l >> 3) & 1) * 8;   // row within 16-block
        int l7 = l & 7;
#pragma unroll
        for (int mt2 = 0; mt2 < 2; mt2++) {
            int m0 = (wid * 2 + mt2) * 16;
#pragma unroll
            for (int kt = 0; kt < 4; kt++) {
                uint32_t chunk = (uint32_t)((kt * 2 + (l >> 4)) ^ l7);
                ldsm4(A[mt2][kt], sXa + (uint32_t)(m0 + arow) * 128 + (chunk << 4));
            }
        }
    }

    const float* biases[3] = {bq, bk, bv};
    __nv_bfloat16* outs[3] = {g_Q + (size_t)n * HW * C + (size_t)p0 * C,
                              g_Kb + (size_t)n * HW * C + (size_t)p0 * C,
                              g_V + (size_t)n * HW * C + (size_t)p0 * C};
    float scales[3] = {QSCALE, 1.f, 1.f};

    int brow = l & 7;                 // B-frag row within ntile
    uint32_t bx0 = (uint32_t)(((0 + (l >> 3)) ^ brow) << 4);
    uint32_t bx4 = (uint32_t)(((4 + (l >> 3)) ^ brow) << 4);

#pragma unroll
    for (int w = 0; w < 3; w++) {
        uint32_t sWa = smem_u32(sW[w]);
        float acc[2][8][4];
#pragma unroll
        for (int a = 0; a < 2; a++)
#pragma unroll
            for (int b = 0; b < 8; b++)
#pragma unroll
                for (int cc = 0; cc < 4; cc++) acc[a][b][cc] = 0.f;

#pragma unroll
        for (int nt = 0; nt < 8; nt++) {
            uint32_t base = sWa + (uint32_t)(nt * 8 + brow) * 128;
            uint32_t B[8];
            ldsm4(B, base + bx0);      // ktiles 0,1
            ldsm4(B + 4, base + bx4);  // ktiles 2,3
#pragma unroll
            for (int mt2 = 0; mt2 < 2; mt2++) {
                mma16816(acc[mt2][nt], A[mt2][0], B[0], B[1]);
                mma16816(acc[mt2][nt], A[mt2][1], B[2], B[3]);
                mma16816(acc[mt2][nt], A[mt2][2], B[4], B[5]);
                mma16816(acc[mt2][nt], A[mt2][3], B[6], B[7]);
            }
        }
        // epilogue: add bias, scale, store bf16 [p][o]
        const float* bias = biases[w];
        float s = scales[w];
        __nv_bfloat16* op = outs[w];
#pragma unroll
        for (int nt = 0; nt < 8; nt++) {
            int col = nt * 8 + (l & 3) * 2;
            float2 bb = *reinterpret_cast<const float2*>(bias + col);
#pragma unroll
            for (int mt2 = 0; mt2 < 2; mt2++) {
                int row0 = (wid * 2 + mt2) * 16 + (l >> 2);
                uint32_t pk0 = packbf((acc[mt2][nt][0] + bb.x) * s, (acc[mt2][nt][1] + bb.y) * s);
                uint32_t pk1 = packbf((acc[mt2][nt][2] + bb.x) * s, (acc[mt2][nt][3] + bb.y) * s);
                *reinterpret_cast<uint32_t*>(op + (size_t)row0 * C + col) = pk0;
                *reinterpret_cast<uint32_t*>(op + (size_t)(row0 + 8) * C + col) = pk1;
            }
        }
    }
}

// ---------- kernel 3: flash attention on mma.sync + ldmatrix ----------
constexpr int ROWB = 144;  // 64 ch * 2B padded to 144B -> conflict-free ldmatrix rows

__global__ __launch_bounds__(128) void attn_kernel() {
    __shared__ __align__(16) char sK[2][KT * ROWB];  // [key][ch]
    __shared__ __align__(16) char sV[2][KT * ROWB];  // [key][ch]  (same layout as K)
    int t = threadIdx.x, wid = t >> 5, lane = t & 31;
    int n = blockIdx.y, qt = blockIdx.x;
    int qrow0 = qt * QT + wid * 16;
    int m = lane >> 2;            // row within fragment
    int qp = (lane & 3) * 2;      // col pair base

    const __nv_bfloat16* Kg = g_Kb + (size_t)n * HW * C;        // [j][c]
    const __nv_bfloat16* Vg = g_V + (size_t)n * HW * C;         // [j][c]

    uint32_t lds_off = (uint32_t)((lane & 7) * ROWB + (lane >> 3) * 16);                 // non-trans
    uint32_t ldt_off = (uint32_t)(((lane & 7) + ((lane >> 3) & 1) * 8) * ROWB + (lane >> 4) * 16); // trans
    uint32_t sKa = smem_u32(sK);
    uint32_t sVa = smem_u32(sV);

    // Q fragments (loop-invariant)
    uint32_t qa[4][4];
    {
        const __nv_bfloat16* Qb = g_Q + ((size_t)n * HW + qrow0) * C;
#pragma unroll
        for (int kb = 0; kb < 4; kb++) {
            qa[kb][0] = *(const uint32_t*)(Qb + (size_t)m * C + kb * 16 + qp);
            qa[kb][1] = *(const uint32_t*)(Qb + (size_t)(m + 8) * C + kb * 16 + qp);
            qa[kb][2] = *(const uint32_t*)(Qb + (size_t)m * C + kb * 16 + 8 + qp);
            qa[kb][3] = *(const uint32_t*)(Qb + (size_t)(m + 8) * C + kb * 16 + 8 + qp);
        }
    }

    float oacc[8][4];
#pragma unroll
    for (int i = 0; i < 8; i++)
#pragma unroll
        for (int j = 0; j < 4; j++) oacc[i][j] = 0.f;
    float lsum0 = 0.f, lsum1 = 0.f;

    auto prefetch = [&](int b, int kt) {
#pragma unroll
        for (int r = 0; r < 4; r++) {
            int ch = t + r * 128;           // 0..511 : 16B chunks
            int row = ch >> 3, col = ch & 7;
            cp_async16(sKa + (uint32_t)(b * KT * ROWB + row * ROWB + col * 16),
                       Kg + ((size_t)(kt * KT + row)) * C + col * 8);
            cp_async16(sVa + (uint32_t)(b * KT * ROWB + row * ROWB + col * 16),
                       Vg + ((size_t)(kt * KT + row)) * C + col * 8);
        }
        cp_commit();
    };

    prefetch(0, 0);

    for (int kt = 0; kt < NKT; kt++) {
        asm volatile("cp.async.wait_group 0;");
        __syncthreads();
        if (kt + 1 < NKT) prefetch((kt + 1) & 1, kt + 1);

        uint32_t kb_a = sKa + (uint32_t)((kt & 1) * KT * ROWB) + lds_off;
        uint32_t vb_a = sVa + (uint32_t)((kt & 1) * KT * ROWB) + ldt_off;

        // MMA1: S[16 x 64keys] = Q * K^T
        float sacc[8][4];
#pragma unroll
        for (int nt = 0; nt < 8; nt++) {
#pragma unroll
            for (int j = 0; j < 4; j++) sacc[nt][j] = 0.f;
            uint32_t B[8];
            ldsm4(B, kb_a + nt * 8 * ROWB);
            ldsm4(B + 4, kb_a + nt * 8 * ROWB + 64);
            mma16816(sacc[nt], qa[0], B[0], B[1]);
            mma16816(sacc[nt], qa[1], B[2], B[3]);
            mma16816(sacc[nt], qa[2], B[4], B[5]);
            mma16816(sacc[nt], qa[3], B[6], B[7]);
        }

        // exp2 + rowsum + pack into P A-fragments
        uint32_t pa[4][4];
#pragma unroll
        for (int kc = 0; kc < 4; kc++) {
#pragma unroll
            for (int h = 0; h < 2; h++) {
                float e0 = ex2f(sacc[2 * kc + h][0]);
                float e1 = ex2f(sacc[2 * kc + h][1]);
                float e2 = ex2f(sacc[2 * kc + h][2]);
                float e3 = ex2f(sacc[2 * kc + h][3]);
                lsum0 += e0 + e1;
                lsum1 += e2 + e3;
                pa[kc][h * 2 + 0] = packbf(e0, e1);
                pa[kc][h * 2 + 1] = packbf(e2, e3);
            }
        }

        // MMA2: O[16 x 64ch] += P * V  (V [j][c] via ldmatrix.trans)
#pragma unroll
        for (int np = 0; np < 4; np++) {
#pragma unroll
            for (int kc = 0; kc < 4; kc++) {
                uint32_t B[4];
                ldsm4t(B, vb_a + (uint32_t)(kc * 16 * ROWB + np * 32));
                mma16816(oacc[2 * np], pa[kc], B[0], B[1]);
                mma16816(oacc[2 * np + 1], pa[kc], B[2], B[3]);
            }
        }
    }

    lsum0 += __shfl_xor_sync(0xffffffffu, lsum0, 1);
    lsum0 += __shfl_xor_sync(0xffffffffu, lsum0, 2);
    lsum1 += __shfl_xor_sync(0xffffffffu, lsum1, 1);
    lsum1 += __shfl_xor_sync(0xffffffffu, lsum1, 2);
    float inv0 = 1.f / lsum0, inv1 = 1.f / lsum1;

    float* orow0 = g_O + ((size_t)n * HW + qrow0 + m) * C;
    float* orow1 = orow0 + 8 * C;
#pragma unroll
    for (int ct = 0; ct < 8; ct++) {
        int col = ct * 8 + qp;
        float2 v0 = make_float2(oacc[ct][0] * inv0, oacc[ct][1] * inv0);
        float2 v1 = make_float2(oacc[ct][2] * inv1, oacc[ct][3] * inv1);
        *reinterpret_cast<float2*>(orow0 + col) = v0;
        *reinterpret_cast<float2*>(orow1 + col) = v1;
    }
}

// ---------- kernel 4: output conv + residual (x prefetched early) ----------
constexpr int OP = 64;   // positions per block
__global__ __launch_bounds__(256) void out_kernel(
    const float* __restrict__ x, const float* __restrict__ wo,
    const float* __restrict__ bo, float* __restrict__ out) {
    __shared__ float sW[C * C];        // transposed: sW[c*64+o]
    __shared__ __align__(16) float sv[C][OP];
    int t = threadIdx.x;
    int n = blockIdx.y;
    int p0 = blockIdx.x * OP;
    int g = t >> 6, pl = t & 63, p = p0 + pl;

    // prefetch residual x early (overlaps staging + compute)
    float xv[16];
    const float* xb = x + (size_t)n * C * HW + p;
#pragma unroll
    for (int o = 0; o < 16; o++) xv[o] = xb[(size_t)(g * 16 + o) * HW];

    for (int j = t; j < C * C; j += 256) sW[(j & 63) * C + (j >> 6)] = wo[j];
    {
        const float* Ob = g_O + (size_t)n * C * HW + p0;   // raw-reshape view [n][c][p]
        for (int j = t; j < C * 16; j += 256) {
            int c = j >> 4, w = j & 15;
            float4 v = *reinterpret_cast<const float4*>(Ob + (size_t)c * HW + w * 4);
            *reinterpret_cast<float4*>(&sv[c][w * 4]) = v;
        }
    }
    __syncthreads();

    float acc[16];
#pragma unroll
    for (int o = 0; o < 16; o++) acc[o] = bo[g * 16 + o];
#pragma unroll
    for (int c = 0; c < C; c++) {
        float v = sv[c][pl];
#pragma unroll
        for (int o = 0; o < 16; o++) acc[o] += sW[c * C + g * 16 + o] * v;
    }
    float* ob = out + (size_t)n * C * HW + p;
#pragma unroll
    for (int o = 0; o < 16; o++)
        ob[(size_t)(g * 16 + o) * HW] = acc[o] + xv[o];
}

extern "C" void kernel_launch(void* const* d_in, const int* in_sizes, int n_in,
                              void* d_out, int out_size) {
    const float* x     = (const float*)d_in[0];
    const float* gamma = (const float*)d_in[1];
    const float* beta  = (const float*)d_in[2];
    const float* wq    = (const float*)d_in[3];
    const float* bq    = (const float*)d_in[4];
    const float* wk    = (const float*)d_in[5];
    const float* bk    = (const float*)d_in[6];
    const float* wv    = (const float*)d_in[7];
    const float* bv    = (const float*)d_in[8];
    const float* wo    = (const float*)d_in[9];
    const float* bo    = (const float*)d_in[10];
    float* out = (float*)d_out;

    bn_part<<<512, 256>>>(x);
    bn_fin<<<1, 64>>>(gamma, beta);
    qkv_kernel<<<dim3(HW / 128, NB), 128>>>(x, wq, bq, wk, bk, wv, bv);
    attn_kernel<<<dim3(HW / QT, NB), 128>>>();
    out_kernel<<<dim3(HW / OP, NB), 256>>>(x, wo, bo, out);
}